// round 5
// baseline (speedup 1.0000x reference)
#include <cuda_runtime.h>
#include <cstdint>

// ============================================================================
// out = gelu( x @ ((fc1_w^T @ fc2_w^T + b) * mask) )   — all fp32
//   x [49152,1024], fc1 [4096(d),1024(s)], fc2 [1024(t),4096(d)]
//   bias[1024], mask[1024(s),1024(t)]
//
// Legacy mma.sync tf32 path (compute_103 target: no tcgen05).
// Weights pre-rounded to tf32 (RNA). x left raw (HW truncation, small bias).
// Mainloop: 3-stage cp.async + double-buffered ldmatrix fragments.
// 512 threads/CTA, warp tile 32x32 (32 accums) -> regs free for frag pipeline.
// ============================================================================

__device__ float g_fc1T[1024 * 4096];
__device__ float g_fc2r[1024 * 4096];
__device__ float g_part[8 * 1024 * 1024];
__device__ float g_attnT[1024 * 1024];

// ---------------- helpers ---------------------------------------------------
__device__ __forceinline__ uint32_t smem_u32(const void* p) {
    uint32_t a;
    asm("{ .reg .u64 t; cvta.to.shared.u64 t, %1; cvt.u32.u64 %0, t; }" : "=r"(a) : "l"(p));
    return a;
}
#define CP_ASYNC16(sdst, gsrc) \
    asm volatile("cp.async.cg.shared.global [%0], [%1], 16;" :: "r"(sdst), "l"(gsrc) : "memory")
#define CP_COMMIT() asm volatile("cp.async.commit_group;" ::: "memory")
#define CP_WAIT1()  asm volatile("cp.async.wait_group 1;" ::: "memory")
#define CP_WAIT0()  asm volatile("cp.async.wait_group 0;" ::: "memory")
#define SWZ128(off) ((off) ^ (((off) >> 3) & 0x70))

__device__ __forceinline__ void ldsm_x4(uint32_t* r, uint32_t addr) {
    asm volatile("ldmatrix.sync.aligned.m8n8.x4.shared.b16 {%0,%1,%2,%3}, [%4];"
                 : "=r"(r[0]), "=r"(r[1]), "=r"(r[2]), "=r"(r[3]) : "r"(addr));
}
__device__ __forceinline__ float f2tf32f(float x) {
    uint32_t r;
    asm("cvt.rna.tf32.f32 %0, %1;" : "=r"(r) : "f"(x));
    return __uint_as_float(r);
}
__device__ __forceinline__ void mma_tf32(float c[4], const uint32_t a[4], const uint32_t* b) {
    asm volatile(
        "mma.sync.aligned.m16n8k8.row.col.f32.tf32.tf32.f32 "
        "{%0,%1,%2,%3}, {%4,%5,%6,%7}, {%8,%9}, {%0,%1,%2,%3};"
        : "+f"(c[0]), "+f"(c[1]), "+f"(c[2]), "+f"(c[3])
        : "r"(a[0]), "r"(a[1]), "r"(a[2]), "r"(a[3]), "r"(b[0]), "r"(b[1]));
}
__device__ __forceinline__ float gelu_exact(float u) {
    return 0.5f * u * (1.0f + erff(u * 0.7071067811865476f));
}

// ---------------------------------------------------------------------------
// Tiled GEMM: CTA 128(m) x 128(n), 512 threads, warp tile 32x32.
// K chunks of 32 floats, 3-stage cp.async, fragment double buffering.
// A [*,lda], B [*,ldb] k-major, C = A·B^T. EPI=1: gelu; EPI=0: raw.
// blockIdx.z = split-K slice.
// ---------------------------------------------------------------------------
constexpr int STAGES = 3;
constexpr int TBYTES = 128 * 128;  // one operand tile stage: 128 rows x 128B

template <int EPI>
__global__ __launch_bounds__(512, 1) void tc_gemm(
    const float* __restrict__ A, const float* __restrict__ B, float* __restrict__ C,
    int M, int N, int lda, int ldb, int kSplit)
{
    extern __shared__ __align__(1024) char smem[];
    const uint32_t sb = smem_u32(smem);
    const int tid  = threadIdx.x;
    const int lane = tid & 31;
    const int wid  = tid >> 5;           // 0..15
    const int wm   = (wid & 3) * 32;
    const int wn   = (wid >> 2) * 32;
    const size_t bm = (size_t)blockIdx.y * 128;
    const size_t bn = (size_t)blockIdx.x * 128;

    const float* Ab = A + (size_t)blockIdx.z * kSplit;
    const float* Bb = B + (size_t)blockIdx.z * kSplit;
    float* Cb = C + (size_t)blockIdx.z * ((size_t)M * N);

    const int nk = kSplit / 32;

    const int lr = tid >> 3;             // 0..63
    const int lc = tid & 7;
    auto issue = [&](int chunk) {
        const int buf = chunk % STAGES;
        const uint32_t aBase = sb + buf * TBYTES;
        const uint32_t bBase = sb + STAGES * TBYTES + buf * TBYTES;
        const float* ga = Ab + (bm + lr) * (size_t)lda + chunk * 32 + lc * 4;
        const float* gb = Bb + (bn + lr) * (size_t)ldb + chunk * 32 + lc * 4;
#pragma unroll
        for (int j = 0; j < 2; j++) {
            CP_ASYNC16(aBase + SWZ128((lr + j * 64) * 128 + lc * 16), ga + (size_t)(j * 64) * lda);
            CP_ASYNC16(bBase + SWZ128((lr + j * 64) * 128 + lc * 16), gb + (size_t)(j * 64) * ldb);
        }
        CP_COMMIT();
    };

    float c[2][4][4];
#pragma unroll
    for (int im = 0; im < 2; im++)
#pragma unroll
        for (int in = 0; in < 4; in++)
#pragma unroll
            for (int q = 0; q < 4; q++) c[im][in][q] = 0.0f;

    issue(0);
    issue(1);

    // ldmatrix lane addressing (b16 x4 trick, one x4 = 16 rows x 8 f32-k):
    const int aRow = lane & 15;
    const int aKo  = ((lane >> 4) & 1) * 16;
    const int bRow = (lane & 7) + ((lane >> 4) << 3);
    const int bKo  = ((lane >> 3) & 1) * 16;

    auto loadA = [&](uint32_t (*f)[4], uint32_t aS, int ks) {
#pragma unroll
        for (int h = 0; h < 2; h++)
            ldsm_x4(f[h], aS + SWZ128((wm + h * 16 + aRow) * 128 + ks * 32 + aKo));
    };
    auto loadB = [&](uint32_t (*f)[4], uint32_t bS, int ks) {
#pragma unroll
        for (int h = 0; h < 2; h++)
            ldsm_x4(f[h], bS + SWZ128((wn + h * 16 + bRow) * 128 + ks * 32 + bKo));
    };

    for (int i = 0; i < nk; i++) {
        if (i + 1 < nk) { CP_WAIT1(); } else { CP_WAIT0(); }
        __syncthreads();
        if (i + 2 < nk) issue(i + 2);

        const int buf = i % STAGES;
        const uint32_t aS = sb + buf * TBYTES;
        const uint32_t bS = sb + STAGES * TBYTES + buf * TBYTES;

        uint32_t af[2][2][4], bf[2][2][4];   // [pingpong][half][4]
        loadA(af[0], aS, 0);
        loadB(bf[0], bS, 0);
#pragma unroll
        for (int ks = 0; ks < 4; ks++) {
            const int cur = ks & 1, nxt = cur ^ 1;
            if (ks < 3) {                     // prefetch ks+1 while MMAing ks
                loadA(af[nxt], aS, ks + 1);
                loadB(bf[nxt], bS, ks + 1);
            }
#pragma unroll
            for (int im = 0; im < 2; im++) {
#pragma unroll
                for (int h = 0; h < 2; h++) {
                    mma_tf32(c[im][h * 2 + 0], af[cur][im], &bf[cur][h][0]);
                    mma_tf32(c[im][h * 2 + 1], af[cur][im], &bf[cur][h][2]);
                }
            }
        }
    }

    // ---------------- epilogue ----------------
    const int g  = lane >> 2;
    const int tg = lane & 3;
#pragma unroll
    for (int im = 0; im < 2; im++) {
#pragma unroll
        for (int in = 0; in < 4; in++) {
            const size_t r0 = bm + wm + im * 16 + g;
            const size_t r1 = r0 + 8;
            const size_t cc = bn + wn + in * 8 + tg * 2;
            float v0 = c[im][in][0], v1 = c[im][in][1];
            float v2 = c[im][in][2], v3 = c[im][in][3];
            if (EPI == 1) {
                v0 = gelu_exact(v0); v1 = gelu_exact(v1);
                v2 = gelu_exact(v2); v3 = gelu_exact(v3);
            }
            *reinterpret_cast<float2*>(Cb + r0 * N + cc) = make_float2(v0, v1);
            *reinterpret_cast<float2*>(Cb + r1 * N + cc) = make_float2(v2, v3);
        }
    }
}

// --------------- tf32 pre-round pass: out[i] = rna_tf32(in[i]) --------------
__global__ __launch_bounds__(256) void round_pass(const float4* __restrict__ in,
                                                  float4* __restrict__ out, int n4)
{
    int i = blockIdx.x * 256 + threadIdx.x;
    int stride = gridDim.x * 256;
    for (; i < n4; i += stride) {
        float4 v = in[i];
        v.x = f2tf32f(v.x); v.y = f2tf32f(v.y);
        v.z = f2tf32f(v.z); v.w = f2tf32f(v.w);
        out[i] = v;
    }
}

// ------- fc1 transpose + round: [4096,1024] -> [1024,4096] (tf32) -----------
__global__ void transpose_k(const float* __restrict__ in, float* __restrict__ out,
                            int R, int Cc)
{
    __shared__ float t[32][33];
    int bx = blockIdx.x * 32;
    int by = blockIdx.y * 32;
    int x = threadIdx.x, y = threadIdx.y;
#pragma unroll
    for (int j = 0; j < 32; j += 8)
        t[y + j][x] = f2tf32f(in[(size_t)(by + y + j) * Cc + bx + x]);
    __syncthreads();
#pragma unroll
    for (int j = 0; j < 32; j += 8)
        out[(size_t)(bx + y + j) * R + by + x] = t[x][y + j];
}

// fixup: attnT[t][s] = rna_tf32( (sum_sk part[sk][s][t] + bias[t]) * mask[s][t] )
__global__ void fixup_k(const float* __restrict__ part, const float* __restrict__ bias,
                        const float* __restrict__ mask, float* __restrict__ attnT)
{
    __shared__ float t[32][33];
    int bt = blockIdx.x * 32;
    int bs = blockIdx.y * 32;
    int x = threadIdx.x, y = threadIdx.y;
#pragma unroll
    for (int j = 0; j < 32; j += 8) {
        int s = bs + y + j, tc = bt + x;
        size_t idx = (size_t)s * 1024 + tc;
        float v = 0.0f;
#pragma unroll
        for (int sk = 0; sk < 8; sk++)
            v += part[idx + (size_t)sk * 1048576];
        v = (v + bias[tc]) * mask[idx];
        t[y + j][x] = f2tf32f(v);
    }
    __syncthreads();
#pragma unroll
    for (int j = 0; j < 32; j += 8)
        attnT[(size_t)(bt + y + j) * 1024 + bs + x] = t[x][y + j];
}

// ---------------------------------------------------------------------------
extern "C" void kernel_launch(void* const* d_in, const int* in_sizes, int n_in,
                              void* d_out, int out_size)
{
    const float* x    = (const float*)d_in[0];
    const float* fc1  = (const float*)d_in[1];
    const float* fc2  = (const float*)d_in[2];
    const float* bias = (const float*)d_in[3];
    const float* mask = (const float*)d_in[4];
    float* out = (float*)d_out;

    float *fc1T, *fc2r, *part, *attnT;
    cudaGetSymbolAddress((void**)&fc1T, g_fc1T);
    cudaGetSymbolAddress((void**)&fc2r, g_fc2r);
    cudaGetSymbolAddress((void**)&part, g_part);
    cudaGetSymbolAddress((void**)&attnT, g_attnT);

    constexpr int SMEM = 2 * STAGES * TBYTES;   // 98304
    cudaFuncSetAttribute(tc_gemm<0>, cudaFuncAttributeMaxDynamicSharedMemorySize, SMEM);
    cudaFuncSetAttribute(tc_gemm<1>, cudaFuncAttributeMaxDynamicSharedMemorySize, SMEM);

    // Pre-round weights to tf32 (RNA). x stays raw (HW truncation in MMA).
    round_pass<<<512, 256>>>((const float4*)fc2, (float4*)fc2r, 1024 * 4096 / 4);

    // fc1T[s][d] = round(fc1[d][s])
    transpose_k<<<dim3(32, 128), dim3(32, 8)>>>(fc1, fc1T, 4096, 1024);

    // GEMM1 split-K=8: part[sk] = fc1T · fc2r^T over k slice
    tc_gemm<0><<<dim3(8, 8, 8), 512, SMEM>>>(fc1T, fc2r, part,
                                             1024, 1024, 4096, 4096, 512);

    // reduce + bias + mask + transpose + round -> attnT [t][s]
    fixup_k<<<dim3(32, 32), dim3(32, 8)>>>(part, bias, mask, attnT);

    // GEMM2: out = gelu(x · attnT^T)
    tc_gemm<1><<<dim3(8, 384, 1), 512, SMEM>>>(x, attnT, out,
                                               49152, 1024, 1024, 1024, 1024);
}

// round 6
// speedup vs baseline: 1.9053x; 1.9053x over previous
#include <cuda_runtime.h>
#include <cuda_fp16.h>
#include <cstdint>

// ============================================================================
// out = gelu( x @ ((fc1_w^T @ fc2_w^T + b) * mask) )   — fp32 in/out
// fp16 mma.sync.m16n8k16 path (same 10-bit mantissa as tf32, 2x throughput).
//   cvt x  -> g_xh   [49152,1024] half
//   cvt fc2-> g_fc2h [1024,4096]  half
//   transpose+cvt fc1 -> g_fc1T [1024,4096] half
//   GEMM1 split-K=4 -> g_part fp32; fixup -> g_attnT [t][s] half
//   GEMM2: out = gelu(xh · attnT^T)
// ============================================================================

__device__ __half g_xh[49152 * 1024];
__device__ __half g_fc1T[1024 * 4096];
__device__ __half g_fc2h[1024 * 4096];
__device__ float  g_part[4 * 1024 * 1024];
__device__ __half g_attnT[1024 * 1024];

// ---------------- helpers ---------------------------------------------------
__device__ __forceinline__ uint32_t smem_u32(const void* p) {
    uint32_t a;
    asm("{ .reg .u64 t; cvta.to.shared.u64 t, %1; cvt.u32.u64 %0, t; }" : "=r"(a) : "l"(p));
    return a;
}
#define CP_ASYNC16(sdst, gsrc) \
    asm volatile("cp.async.cg.shared.global [%0], [%1], 16;" :: "r"(sdst), "l"(gsrc) : "memory")
#define CP_COMMIT() asm volatile("cp.async.commit_group;" ::: "memory")
#define CP_WAIT1()  asm volatile("cp.async.wait_group 1;" ::: "memory")
#define CP_WAIT0()  asm volatile("cp.async.wait_group 0;" ::: "memory")
#define SWZ128(off) ((off) ^ (((off) >> 3) & 0x70))

__device__ __forceinline__ void ldsm_x4(uint32_t* r, uint32_t addr) {
    asm volatile("ldmatrix.sync.aligned.m8n8.x4.shared.b16 {%0,%1,%2,%3}, [%4];"
                 : "=r"(r[0]), "=r"(r[1]), "=r"(r[2]), "=r"(r[3]) : "r"(addr));
}
// fp16 MMA, fp32 accumulate: C[16x8] += A[16x16] * B[16x8]
__device__ __forceinline__ void mma_f16(float c[4], const uint32_t a[4], const uint32_t* b) {
    asm volatile(
        "mma.sync.aligned.m16n8k16.row.col.f32.f16.f16.f32 "
        "{%0,%1,%2,%3}, {%4,%5,%6,%7}, {%8,%9}, {%0,%1,%2,%3};"
        : "+f"(c[0]), "+f"(c[1]), "+f"(c[2]), "+f"(c[3])
        : "r"(a[0]), "r"(a[1]), "r"(a[2]), "r"(a[3]), "r"(b[0]), "r"(b[1]));
}
__device__ __forceinline__ float gelu_exact(float u) {
    return 0.5f * u * (1.0f + erff(u * 0.7071067811865476f));
}

// ---------------------------------------------------------------------------
// fp16 GEMM: CTA 128(m) x 128(n), 256 threads, warp tile 32x64.
// K chunks of 64 halfs (128B rows, SW128), 3-stage cp.async.
// A [*,lda], B [*,ldb] k-major halfs, C = A·B^T fp32.
// EPI=1: gelu store; EPI=0: raw store. blockIdx.z = split-K slice.
// ---------------------------------------------------------------------------
constexpr int STAGES = 3;
constexpr int TBYTES = 128 * 128;   // 128 rows x 64 halfs

template <int EPI>
__global__ __launch_bounds__(256, 2) void hgemm(
    const __half* __restrict__ A, const __half* __restrict__ B, float* __restrict__ C,
    int M, int N, int lda, int ldb, int kSplit)
{
    extern __shared__ __align__(1024) char smem[];
    const uint32_t sb = smem_u32(smem);
    const int tid  = threadIdx.x;
    const int lane = tid & 31;
    const int wid  = tid >> 5;
    const int wm   = (wid & 3) * 32;
    const int wn   = (wid >> 2) * 64;
    const size_t bm = (size_t)blockIdx.y * 128;
    const size_t bn = (size_t)blockIdx.x * 128;

    const __half* Ab = A + (size_t)blockIdx.z * kSplit;
    const __half* Bb = B + (size_t)blockIdx.z * kSplit;
    float* Cb = C + (size_t)blockIdx.z * ((size_t)M * N);

    const int nk = kSplit / 64;

    const int lr = tid >> 3;        // 0..31
    const int lc = tid & 7;         // 16B (8-half) column
    auto issue = [&](int chunk) {
        const int buf = chunk % STAGES;
        const uint32_t aBase = sb + buf * TBYTES;
        const uint32_t bBase = sb + STAGES * TBYTES + buf * TBYTES;
        const __half* ga = Ab + (bm + lr) * (size_t)lda + chunk * 64 + lc * 8;
        const __half* gb = Bb + (bn + lr) * (size_t)ldb + chunk * 64 + lc * 8;
#pragma unroll
        for (int j = 0; j < 4; j++) {
            CP_ASYNC16(aBase + SWZ128((lr + j * 32) * 128 + lc * 16), ga + (size_t)(j * 32) * lda);
            CP_ASYNC16(bBase + SWZ128((lr + j * 32) * 128 + lc * 16), gb + (size_t)(j * 32) * ldb);
        }
        CP_COMMIT();
    };

    float c[2][8][4];
#pragma unroll
    for (int im = 0; im < 2; im++)
#pragma unroll
        for (int in = 0; in < 8; in++)
#pragma unroll
            for (int q = 0; q < 4; q++) c[im][in][q] = 0.0f;

    issue(0);
    issue(1);

    // ldmatrix addressing:
    // A (16m x 16k frag): row = (lane&15), +16B for lanes 16-31 -> mma A reg order
    //   {m0-7/k0-7, m8-15/k0-7, m0-7/k8-15, m8-15/k8-15}.
    // B (n-major rows, k contiguous): x4 covers 16n x 16k:
    //   lanes0-7: n0-7/k0-7 | 8-15: n0-7/k8-15 | 16-23: n8-15/k0-7 | 24-31: n8-15/k8-15
    //   -> regs {b0(n0-7), b1(n0-7), b0(n8-15), b1(n8-15)}.
    const int aRow = lane & 15;
    const int aKo  = ((lane >> 4) & 1) * 16;
    const int bRow = (lane & 7) + ((lane >> 4) << 3);
    const int bKo  = ((lane >> 3) & 1) * 16;

    for (int i = 0; i < nk; i++) {
        if (i + 1 < nk) { CP_WAIT1(); } else { CP_WAIT0(); }
        __syncthreads();
        if (i + 2 < nk) issue(i + 2);

        const int buf = i % STAGES;
        const uint32_t aS = sb + buf * TBYTES;
        const uint32_t bS = sb + STAGES * TBYTES + buf * TBYTES;

#pragma unroll
        for (int ks = 0; ks < 4; ks++) {   // 4 x k16 (32B each) per 128B row chunk
            uint32_t af[2][4], bf[4][4];
#pragma unroll
            for (int im = 0; im < 2; im++)
                ldsm_x4(af[im], aS + SWZ128((wm + im * 16 + aRow) * 128 + ks * 32 + aKo));
#pragma unroll
            for (int nb = 0; nb < 4; nb++)
                ldsm_x4(bf[nb], bS + SWZ128((wn + nb * 16 + bRow) * 128 + ks * 32 + bKo));
#pragma unroll
            for (int im = 0; im < 2; im++)
#pragma unroll
                for (int nb = 0; nb < 4; nb++) {
                    mma_f16(c[im][nb * 2 + 0], af[im], &bf[nb][0]);
                    mma_f16(c[im][nb * 2 + 1], af[im], &bf[nb][2]);
                }
        }
    }

    // ---------------- epilogue ----------------
    const int g  = lane >> 2;
    const int tg = lane & 3;
#pragma unroll
    for (int im = 0; im < 2; im++) {
#pragma unroll
        for (int in = 0; in < 8; in++) {
            const size_t r0 = bm + wm + im * 16 + g;
            const size_t r1 = r0 + 8;
            const size_t cc = bn + wn + in * 8 + tg * 2;
            float v0 = c[im][in][0], v1 = c[im][in][1];
            float v2 = c[im][in][2], v3 = c[im][in][3];
            if (EPI == 1) {
                v0 = gelu_exact(v0); v1 = gelu_exact(v1);
                v2 = gelu_exact(v2); v3 = gelu_exact(v3);
            }
            *reinterpret_cast<float2*>(Cb + r0 * N + cc) = make_float2(v0, v1);
            *reinterpret_cast<float2*>(Cb + r1 * N + cc) = make_float2(v2, v3);
        }
    }
}

// --------------- fp32 -> fp16 conversion pass --------------------------------
__global__ __launch_bounds__(256) void cvt_half(const float4* __restrict__ in,
                                                __half2* __restrict__ out, int n4)
{
    int i = blockIdx.x * 256 + threadIdx.x;
    int stride = gridDim.x * 256;
    for (; i < n4; i += stride) {
        float4 v = in[i];
        out[i * 2 + 0] = __floats2half2_rn(v.x, v.y);
        out[i * 2 + 1] = __floats2half2_rn(v.z, v.w);
    }
}

// ------- fc1 transpose + cvt: [4096,1024] f32 -> [1024,4096] half ------------
__global__ void transpose_k(const float* __restrict__ in, __half* __restrict__ out,
                            int R, int Cc)
{
    __shared__ float t[32][33];
    int bx = blockIdx.x * 32;
    int by = blockIdx.y * 32;
    int x = threadIdx.x, y = threadIdx.y;
#pragma unroll
    for (int j = 0; j < 32; j += 8)
        t[y + j][x] = in[(size_t)(by + y + j) * Cc + bx + x];
    __syncthreads();
#pragma unroll
    for (int j = 0; j < 32; j += 8)
        out[(size_t)(bx + y + j) * R + by + x] = __float2half_rn(t[x][y + j]);
}

// fixup: attnT[t][s] = half( (sum_sk part[sk][s][t] + bias[t]) * mask[s][t] )
__global__ void fixup_k(const float* __restrict__ part, const float* __restrict__ bias,
                        const float* __restrict__ mask, __half* __restrict__ attnT)
{
    __shared__ float t[32][33];
    int bt = blockIdx.x * 32;
    int bs = blockIdx.y * 32;
    int x = threadIdx.x, y = threadIdx.y;
#pragma unroll
    for (int j = 0; j < 32; j += 8) {
        int s = bs + y + j, tc = bt + x;
        size_t idx = (size_t)s * 1024 + tc;
        float v = part[idx] + part[idx + 1048576] + part[idx + 2097152] + part[idx + 3145728];
        v = (v + bias[tc]) * mask[idx];
        t[y + j][x] = v;
    }
    __syncthreads();
#pragma unroll
    for (int j = 0; j < 32; j += 8)
        attnT[(size_t)(bt + y + j) * 1024 + bs + x] = __float2half_rn(t[x][y + j]);
}

// ---------------------------------------------------------------------------
extern "C" void kernel_launch(void* const* d_in, const int* in_sizes, int n_in,
                              void* d_out, int out_size)
{
    const float* x    = (const float*)d_in[0];
    const float* fc1  = (const float*)d_in[1];
    const float* fc2  = (const float*)d_in[2];
    const float* bias = (const float*)d_in[3];
    const float* mask = (const float*)d_in[4];
    float* out = (float*)d_out;

    __half *xh, *fc1T, *fc2h, *attnT;
    float* part;
    cudaGetSymbolAddress((void**)&xh, g_xh);
    cudaGetSymbolAddress((void**)&fc1T, g_fc1T);
    cudaGetSymbolAddress((void**)&fc2h, g_fc2h);
    cudaGetSymbolAddress((void**)&part, g_part);
    cudaGetSymbolAddress((void**)&attnT, g_attnT);

    constexpr int SMEM = 2 * STAGES * TBYTES;   // 98304
    cudaFuncSetAttribute(hgemm<0>, cudaFuncAttributeMaxDynamicSharedMemorySize, SMEM);
    cudaFuncSetAttribute(hgemm<1>, cudaFuncAttributeMaxDynamicSharedMemorySize, SMEM);

    // fp32 -> fp16 operand conversion
    cvt_half<<<4736, 256>>>((const float4*)x, (__half2*)xh, 49152 * 1024 / 4);
    cvt_half<<<1024, 256>>>((const float4*)fc2, (__half2*)fc2h, 1024 * 4096 / 4);

    // fc1T[s][d] = half(fc1[d][s])
    transpose_k<<<dim3(32, 128), dim3(32, 8)>>>(fc1, fc1T, 4096, 1024);

    // GEMM1 split-K=4: part[sk] = fc1T · fc2h^T over k slice
    hgemm<0><<<dim3(8, 8, 4), 256, SMEM>>>(fc1T, fc2h, part,
                                           1024, 1024, 4096, 4096, 1024);

    // reduce + bias + mask + transpose -> attnT [t][s] half
    fixup_k<<<dim3(32, 32), dim3(32, 8)>>>(part, bias, mask, attnT);

    // GEMM2: out = gelu(xh · attnT^T)
    hgemm<1><<<dim3(8, 384, 1), 256, SMEM>>>(xh, attnT, out,
                                             49152, 1024, 1024, 1024, 1024);
}

// round 7
// speedup vs baseline: 1.9638x; 1.0307x over previous
#include <cuda_runtime.h>
#include <cuda_fp16.h>
#include <cstdint>

// ============================================================================
// out = gelu( x @ ((fc1_w^T @ fc2_w^T + b) * mask) )   — fp32 in/out
// fp16 mma.sync.m16n8k16 path. R7: fragment double-buffering across k16 steps
// on the winning 32x64 warp tile (R6 schedule otherwise unchanged).
// ============================================================================

__device__ __half g_xh[49152 * 1024];
__device__ __half g_fc1T[1024 * 4096];
__device__ __half g_fc2h[1024 * 4096];
__device__ float  g_part[4 * 1024 * 1024];
__device__ __half g_attnT[1024 * 1024];

// ---------------- helpers ---------------------------------------------------
__device__ __forceinline__ uint32_t smem_u32(const void* p) {
    uint32_t a;
    asm("{ .reg .u64 t; cvta.to.shared.u64 t, %1; cvt.u32.u64 %0, t; }" : "=r"(a) : "l"(p));
    return a;
}
#define CP_ASYNC16(sdst, gsrc) \
    asm volatile("cp.async.cg.shared.global [%0], [%1], 16;" :: "r"(sdst), "l"(gsrc) : "memory")
#define CP_COMMIT() asm volatile("cp.async.commit_group;" ::: "memory")
#define CP_WAIT1()  asm volatile("cp.async.wait_group 1;" ::: "memory")
#define CP_WAIT0()  asm volatile("cp.async.wait_group 0;" ::: "memory")
#define SWZ128(off) ((off) ^ (((off) >> 3) & 0x70))

__device__ __forceinline__ void ldsm_x4(uint32_t* r, uint32_t addr) {
    asm volatile("ldmatrix.sync.aligned.m8n8.x4.shared.b16 {%0,%1,%2,%3}, [%4];"
                 : "=r"(r[0]), "=r"(r[1]), "=r"(r[2]), "=r"(r[3]) : "r"(addr));
}
// fp16 MMA, fp32 accumulate: C[16x8] += A[16x16] * B[16x8]
__device__ __forceinline__ void mma_f16(float c[4], const uint32_t a[4], const uint32_t* b) {
    asm volatile(
        "mma.sync.aligned.m16n8k16.row.col.f32.f16.f16.f32 "
        "{%0,%1,%2,%3}, {%4,%5,%6,%7}, {%8,%9}, {%0,%1,%2,%3};"
        : "+f"(c[0]), "+f"(c[1]), "+f"(c[2]), "+f"(c[3])
        : "r"(a[0]), "r"(a[1]), "r"(a[2]), "r"(a[3]), "r"(b[0]), "r"(b[1]));
}
__device__ __forceinline__ float gelu_exact(float u) {
    return 0.5f * u * (1.0f + erff(u * 0.7071067811865476f));
}

// ---------------------------------------------------------------------------
// fp16 GEMM: CTA 128(m) x 128(n), 256 threads, warp tile 32x64.
// K chunks of 64 halfs (128B rows, SW128), 3-stage cp.async,
// fragment double-buffering across the 4 k16 sub-steps.
// A [*,lda], B [*,ldb] k-major halfs, C = A·B^T fp32.
// EPI=1: gelu store; EPI=0: raw store. blockIdx.z = split-K slice.
// ---------------------------------------------------------------------------
constexpr int STAGES = 3;
constexpr int TBYTES = 128 * 128;   // 128 rows x 64 halfs

template <int EPI>
__global__ __launch_bounds__(256, 2) void hgemm(
    const __half* __restrict__ A, const __half* __restrict__ B, float* __restrict__ C,
    int M, int N, int lda, int ldb, int kSplit)
{
    extern __shared__ __align__(1024) char smem[];
    const uint32_t sb = smem_u32(smem);
    const int tid  = threadIdx.x;
    const int lane = tid & 31;
    const int wid  = tid >> 5;
    const int wm   = (wid & 3) * 32;
    const int wn   = (wid >> 2) * 64;
    const size_t bm = (size_t)blockIdx.y * 128;
    const size_t bn = (size_t)blockIdx.x * 128;

    const __half* Ab = A + (size_t)blockIdx.z * kSplit;
    const __half* Bb = B + (size_t)blockIdx.z * kSplit;
    float* Cb = C + (size_t)blockIdx.z * ((size_t)M * N);

    const int nk = kSplit / 64;

    const int lr = tid >> 3;        // 0..31
    const int lc = tid & 7;         // 16B (8-half) column
    auto issue = [&](int chunk) {
        const int buf = chunk % STAGES;
        const uint32_t aBase = sb + buf * TBYTES;
        const uint32_t bBase = sb + STAGES * TBYTES + buf * TBYTES;
        const __half* ga = Ab + (bm + lr) * (size_t)lda + chunk * 64 + lc * 8;
        const __half* gb = Bb + (bn + lr) * (size_t)ldb + chunk * 64 + lc * 8;
#pragma unroll
        for (int j = 0; j < 4; j++) {
            CP_ASYNC16(aBase + SWZ128((lr + j * 32) * 128 + lc * 16), ga + (size_t)(j * 32) * lda);
            CP_ASYNC16(bBase + SWZ128((lr + j * 32) * 128 + lc * 16), gb + (size_t)(j * 32) * ldb);
        }
        CP_COMMIT();
    };

    float c[2][8][4];
#pragma unroll
    for (int im = 0; im < 2; im++)
#pragma unroll
        for (int in = 0; in < 8; in++)
#pragma unroll
            for (int q = 0; q < 4; q++) c[im][in][q] = 0.0f;

    issue(0);
    issue(1);

    // ldmatrix addressing (see R6 comments): A x4 = 16m x 16k frag in mma reg
    // order; B x4 = 16n x 16k -> {b0(n0-7), b1(n0-7), b0(n8-15), b1(n8-15)}.
    const int aRow = lane & 15;
    const int aKo  = ((lane >> 4) & 1) * 16;
    const int bRow = (lane & 7) + ((lane >> 4) << 3);
    const int bKo  = ((lane >> 3) & 1) * 16;

    auto loadA = [&](uint32_t (*f)[4], uint32_t aS, int ks) {
#pragma unroll
        for (int im = 0; im < 2; im++)
            ldsm_x4(f[im], aS + SWZ128((wm + im * 16 + aRow) * 128 + ks * 32 + aKo));
    };
    auto loadB = [&](uint32_t (*f)[4], uint32_t bS, int ks) {
#pragma unroll
        for (int nb = 0; nb < 4; nb++)
            ldsm_x4(f[nb], bS + SWZ128((wn + nb * 16 + bRow) * 128 + ks * 32 + bKo));
    };

    for (int i = 0; i < nk; i++) {
        if (i + 1 < nk) { CP_WAIT1(); } else { CP_WAIT0(); }
        __syncthreads();
        if (i + 2 < nk) issue(i + 2);

        const int buf = i % STAGES;
        const uint32_t aS = sb + buf * TBYTES;
        const uint32_t bS = sb + STAGES * TBYTES + buf * TBYTES;

        uint32_t af[2][2][4];   // [pingpong][im][4]
        uint32_t bf[2][4][4];   // [pingpong][nb][4]
        loadA(af[0], aS, 0);
        loadB(bf[0], bS, 0);
#pragma unroll
        for (int ks = 0; ks < 4; ks++) {   // 4 x k16 (32B each) per 128B chunk
            const int cur = ks & 1, nxt = cur ^ 1;
            if (ks < 3) {                  // prefetch ks+1 while MMAing ks
                loadA(af[nxt], aS, ks + 1);
                loadB(bf[nxt], bS, ks + 1);
            }
#pragma unroll
            for (int im = 0; im < 2; im++)
#pragma unroll
                for (int nb = 0; nb < 4; nb++) {
                    mma_f16(c[im][nb * 2 + 0], af[cur][im], &bf[cur][nb][0]);
                    mma_f16(c[im][nb * 2 + 1], af[cur][im], &bf[cur][nb][2]);
                }
        }
    }

    // ---------------- epilogue ----------------
    const int g  = lane >> 2;
    const int tg = lane & 3;
#pragma unroll
    for (int im = 0; im < 2; im++) {
#pragma unroll
        for (int in = 0; in < 8; in++) {
            const size_t r0 = bm + wm + im * 16 + g;
            const size_t r1 = r0 + 8;
            const size_t cc = bn + wn + in * 8 + tg * 2;
            float v0 = c[im][in][0], v1 = c[im][in][1];
            float v2 = c[im][in][2], v3 = c[im][in][3];
            if (EPI == 1) {
                v0 = gelu_exact(v0); v1 = gelu_exact(v1);
                v2 = gelu_exact(v2); v3 = gelu_exact(v3);
            }
            *reinterpret_cast<float2*>(Cb + r0 * N + cc) = make_float2(v0, v1);
            *reinterpret_cast<float2*>(Cb + r1 * N + cc) = make_float2(v2, v3);
        }
    }
}

// --------------- fp32 -> fp16 conversion pass --------------------------------
__global__ __launch_bounds__(256) void cvt_half(const float4* __restrict__ in,
                                                __half2* __restrict__ out, int n4)
{
    int i = blockIdx.x * 256 + threadIdx.x;
    int stride = gridDim.x * 256;
    for (; i < n4; i += stride) {
        float4 v = in[i];
        out[i * 2 + 0] = __floats2half2_rn(v.x, v.y);
        out[i * 2 + 1] = __floats2half2_rn(v.z, v.w);
    }
}

// ------- fc1 transpose + cvt: [4096,1024] f32 -> [1024,4096] half ------------
__global__ void transpose_k(const float* __restrict__ in, __half* __restrict__ out,
                            int R, int Cc)
{
    __shared__ float t[32][33];
    int bx = blockIdx.x * 32;
    int by = blockIdx.y * 32;
    int x = threadIdx.x, y = threadIdx.y;
#pragma unroll
    for (int j = 0; j < 32; j += 8)
        t[y + j][x] = in[(size_t)(by + y + j) * Cc + bx + x];
    __syncthreads();
#pragma unroll
    for (int j = 0; j < 32; j += 8)
        out[(size_t)(bx + y + j) * R + by + x] = __float2half_rn(t[x][y + j]);
}

// fixup: attnT[t][s] = half( (sum_sk part[sk][s][t] + bias[t]) * mask[s][t] )
__global__ void fixup_k(const float* __restrict__ part, const float* __restrict__ bias,
                        const float* __restrict__ mask, __half* __restrict__ attnT)
{
    __shared__ float t[32][33];
    int bt = blockIdx.x * 32;
    int bs = blockIdx.y * 32;
    int x = threadIdx.x, y = threadIdx.y;
#pragma unroll
    for (int j = 0; j < 32; j += 8) {
        int s = bs + y + j, tc = bt + x;
        size_t idx = (size_t)s * 1024 + tc;
        float v = part[idx] + part[idx + 1048576] + part[idx + 2097152] + part[idx + 3145728];
        v = (v + bias[tc]) * mask[idx];
        t[y + j][x] = v;
    }
    __syncthreads();
#pragma unroll
    for (int j = 0; j < 32; j += 8)
        attnT[(size_t)(bt + y + j) * 1024 + bs + x] = __float2half_rn(t[x][y + j]);
}

// ---------------------------------------------------------------------------
extern "C" void kernel_launch(void* const* d_in, const int* in_sizes, int n_in,
                              void* d_out, int out_size)
{
    const float* x    = (const float*)d_in[0];
    const float* fc1  = (const float*)d_in[1];
    const float* fc2  = (const float*)d_in[2];
    const float* bias = (const float*)d_in[3];
    const float* mask = (const float*)d_in[4];
    float* out = (float*)d_out;

    __half *xh, *fc1T, *fc2h, *attnT;
    float* part;
    cudaGetSymbolAddress((void**)&xh, g_xh);
    cudaGetSymbolAddress((void**)&fc1T, g_fc1T);
    cudaGetSymbolAddress((void**)&fc2h, g_fc2h);
    cudaGetSymbolAddress((void**)&part, g_part);
    cudaGetSymbolAddress((void**)&attnT, g_attnT);

    constexpr int SMEM = 2 * STAGES * TBYTES;   // 98304
    cudaFuncSetAttribute(hgemm<0>, cudaFuncAttributeMaxDynamicSharedMemorySize, SMEM);
    cudaFuncSetAttribute(hgemm<1>, cudaFuncAttributeMaxDynamicSharedMemorySize, SMEM);

    // fp32 -> fp16 operand conversion
    cvt_half<<<4736, 256>>>((const float4*)x, (__half2*)xh, 49152 * 1024 / 4);
    cvt_half<<<1024, 256>>>((const float4*)fc2, (__half2*)fc2h, 1024 * 4096 / 4);

    // fc1T[s][d] = half(fc1[d][s])
    transpose_k<<<dim3(32, 128), dim3(32, 8)>>>(fc1, fc1T, 4096, 1024);

    // GEMM1 split-K=4: part[sk] = fc1T · fc2h^T over k slice
    hgemm<0><<<dim3(8, 8, 4), 256, SMEM>>>(fc1T, fc2h, part,
                                           1024, 1024, 4096, 4096, 1024);

    // reduce + bias + mask + transpose -> attnT [t][s] half
    fixup_k<<<dim3(32, 32), dim3(32, 8)>>>(part, bias, mask, attnT);

    // GEMM2: out = gelu(xh · attnT^T)
    hgemm<1><<<dim3(8, 384, 1), 256, SMEM>>>(xh, attnT, out,
                                             49152, 1024, 1024, 1024, 1024);
}